// round 16
// baseline (speedup 1.0000x reference)
#include <cuda_runtime.h>
#include <math.h>

// ---------------- problem constants ----------------
#define NB 4            // batch
#define NC 32           // channels
#define NT 131072       // samples
#define NFR 256         // sig frames
#define SPF 512         // samples per sig frame
#define WS 2048         // window size
#define HOP 1024        // step
#define FR 128          // fft frames per signal
#define KB 1025         // rfft bins
#define BC (NB*NC)      // 128
#define NL 3            // layers
#define NH 1024         // complex FFT length (real 2048 packed)
#define CH 16           // chunks per signal
#define FPC 8           // frames per chunk

// skewed smem indexing: conflict-free for stride-4m scatter stores
#define SKW(i) ((i) + ((i) >> 5))
#define SSZ (NH + (NH >> 5) + 1)   // 1057

// sweep kernel dynamic smem (floats): float2 X[KB]; float AR,AI,BR,BI[SSZ]
#define SWEEP_FLOATS (2*KB + 4*SSZ)
#define SWEEP_BYTES (SWEEP_FLOATS * 4)

// ---------------- device scratch (static: no runtime allocation) ----------------
__device__ float  g_env[NC*SPF];
__device__ float  g_T[NL*NC*KB];
__device__ float  g_x[NL+1][BC*NT];
__device__ float  g_xm[BC*NT];
__device__ float2 g_spec[BC*FR*KB];          // spectra
__device__ float2 g_carry[CH*BC*KB];         // chunk-entry carries (ch=0 unused)
__device__ float2 g_bnd_first[BC*CH*512];    // chunk-first-frame first half (pairs)
__device__ float2 g_bnd_sec[BC*CH*512];      // chunk-last-frame second half (pairs)
__device__ int    g_ident[NL];

// ---------------- init: envelopes ----------------
__global__ void init_kernel(const float* __restrict__ decays) {
    int tid = blockIdx.x * blockDim.x + threadIdx.x;
    if (tid < NC*SPF) {
        int ch = tid / SPF, j = tid - ch*SPF;
        float base = (float)(SPF-1 - j) * (1.0f/(float)(SPF-1));
        g_env[tid] = powf(base, decays[ch]);
    }
}

// ---------------- identity check for mixer matrices ----------------
__global__ void ident_kernel(const float* __restrict__ M) {
    __shared__ int ok;
    if (threadIdx.x == 0) ok = 1;
    __syncthreads();
    const float* m = M + blockIdx.x * NC*NC;
    for (int i = threadIdx.x; i < NC*NC; i += 256) {
        float expect = ((i / NC) == (i % NC)) ? 1.0f : 0.0f;
        if (m[i] != expect) atomicExch(&ok, 0);
    }
    __syncthreads();
    if (threadIdx.x == 0) g_ident[blockIdx.x] = ok;
}

// ---------------- T = transfers @ filter_bank (exploit ~1% sparsity) ----------------
__global__ void tmat_kernel(const float* __restrict__ transfers, const float* __restrict__ fb) {
    int lc  = blockIdx.x;
    int tid = threadIdx.x;
    const float* tr = transfers + (size_t)lc * KB;
    float acc[5] = {0.f,0.f,0.f,0.f,0.f};
    for (int j = 0; j < KB; j++) {
        float t = tr[j];
        if (t != 0.0f) {
            const float* row = fb + (size_t)j * KB;
            #pragma unroll
            for (int u = 0; u < 5; u++) {
                int k = tid + u*256;
                if (k < KB) acc[u] += t * row[k];
            }
        }
    }
    #pragma unroll
    for (int u = 0; u < 5; u++) {
        int k = tid + u*256;
        if (k < KB) g_T[(size_t)lc*KB + k] = acc[u];
    }
}

// ---------------- excitation (float4) ----------------
__global__ void x0_kernel(const float* __restrict__ sig, const float* __restrict__ noise) {
    int idx = blockIdx.x * 256 + threadIdx.x;       // float4 index
    if (idx >= BC*NT/4) return;
    int bc = idx / (NT/4), t4 = idx - bc*(NT/4);
    int t  = t4 * 4;
    int c = bc & (NC-1);
    int f = t >> 9, j = t & 511;
    float s = sig[bc*NFR + f];
    float4 nz = ((const float4*)noise)[t4];
    float4 ev = ((const float4*)g_env)[c*(SPF/4) + (j >> 2)];
    float4 o;
    o.x = s * ev.x * nz.x;  o.y = s * ev.y * nz.y;
    o.z = s * ev.z * nz.z;  o.w = s * ev.w * nz.w;
    ((float4*)(g_x[0] + (size_t)bc*NT))[t4] = o;
}

// ---------------- channel mixing (only runs when mixer_mat != identity) ----------------
__global__ void __launch_bounds__(256) mix_kernel(int layer, const float* __restrict__ M) {
    if (g_ident[layer]) return;
    __shared__ float Ms[NC*NC];
    int b = blockIdx.y, t = blockIdx.x * 256 + threadIdx.x;
    for (int i = threadIdx.x; i < NC*NC; i += 256) Ms[i] = M[i];
    __syncthreads();
    const float* xin = g_x[layer] + (size_t)b*NC*NT + t;
    float xv[NC];
    #pragma unroll
    for (int c = 0; c < NC; c++) xv[c] = xin[(size_t)c*NT];
    float* xo = g_xm + (size_t)b*NC*NT + t;
    #pragma unroll
    for (int d = 0; d < NC; d++) {
        float s = 0.f;
        #pragma unroll
        for (int c = 0; c < NC; c++) s += xv[c] * Ms[c*NC + d];
        xo[(size_t)d*NT] = s;
    }
}

// ---------------- forward radix-4 stage, register twiddle (w = e^{-2pi i j/1024}) ----------------
__device__ __forceinline__ void fwd_stage(const float* sR, const float* sI, float* dR, float* dI,
                                          int lt, int m, int l2m, float wr, float wi) {
    float ar = sR[SKW(lt)],     ai = sI[SKW(lt)];
    float br = sR[SKW(lt+256)], bi = sI[SKW(lt+256)];
    float cr = sR[SKW(lt+512)], ci = sI[SKW(lt+512)];
    float dr = sR[SKW(lt+768)], di = sI[SKW(lt+768)];
    float apcr = ar+cr, apci = ai+ci, amcr = ar-cr, amci = ai-ci;
    float bpdr = br+dr, bpdi = bi+di, bmdr = br-dr, bmdi = bi-di;
    float t1r = amcr + bmdi, t1i = amci - bmdr;
    float t3r = amcr - bmdi, t3i = amci + bmdr;
    float w2r = wr*wr - wi*wi, w2i = 2.0f*wr*wi;
    float w3r = w2r*wr - w2i*wi, w3i = w2r*wi + w2i*wr;
    int q  = lt & (m-1);
    int ob = q + ((lt >> l2m) << (l2m + 2));
    float s2r = apcr - bpdr, s2i = apci - bpdi;
    dR[SKW(ob)]      = apcr + bpdr;       dI[SKW(ob)]      = apci + bpdi;
    dR[SKW(ob+m)]    = t1r*wr - t1i*wi;   dI[SKW(ob+m)]    = t1r*wi + t1i*wr;
    dR[SKW(ob+2*m)]  = s2r*w2r - s2i*w2i; dI[SKW(ob+2*m)]  = s2r*w2i + s2i*w2r;
    dR[SKW(ob+3*m)]  = t3r*w3r - t3i*w3i; dI[SKW(ob+3*m)]  = t3r*w3i + t3i*w3r;
}

// ---------------- forward FFT: one frame per block, all-register twiddles ----------------
__global__ void __launch_bounds__(256) fwd_kernel(int layer) {
    __shared__ float AR[SSZ], AI[SSZ], BR[SSZ], BI[SSZ];
    int blk = blockIdx.x, bc = blk >> 7, f = blk & (FR-1), lt = threadIdx.x;

    // ---- frame-invariant per-thread constants ----
    float cs_, sn_;                        // (cos,sin)(pi lt/512)
    sincospif((float)lt * (1.0f/512.0f), &sn_, &cs_);
    float s0r = cs_, s0i = -sn_;           // stage0 twiddle e^{-2pi i lt/1024}
    float w1r_, w1i_, w2r_, w2i_, w3r_, w3i_;
    { float sn, cs;
      sincospif(-(float)(lt & ~3)  * (1.0f/512.0f), &sn, &cs); w1r_ = cs; w1i_ = sn;
      sincospif(-(float)(lt & ~15) * (1.0f/512.0f), &sn, &cs); w2r_ = cs; w2i_ = sn;
      sincospif(-(float)(lt & ~63) * (1.0f/512.0f), &sn, &cs); w3r_ = cs; w3i_ = sn; }
    float he[4], ho[4];                    // hann at samples 2n / 2n+1, n = lt+256u
    he[0] = 0.5f - 0.5f*cs_; he[1] = 0.5f + 0.5f*sn_;
    he[2] = 0.5f + 0.5f*cs_; he[3] = 0.5f - 0.5f*sn_;
    { float sn, cs; sincospif((float)(2*lt+1) * (1.0f/1024.0f), &sn, &cs);
      ho[0] = 0.5f - 0.5f*cs; ho[1] = 0.5f + 0.5f*sn;
      ho[2] = 0.5f + 0.5f*cs; ho[3] = 0.5f - 0.5f*sn; }
    // unpack rotation e^{-i pi k/1024}, k = lt+256u: V * e^{-i pi u/4}
    const float RC = 0.70710678118654752f;
    float Vr, Vi;
    { float sn, cs; sincospif((float)lt * (1.0f/1024.0f), &sn, &cs); Vr = cs; Vi = -sn; }
    float ucs[4], usn[4];
    ucs[0] = Vr;            usn[0] = Vi;
    ucs[1] = RC*(Vr + Vi);  usn[1] = RC*(Vi - Vr);
    ucs[2] = Vi;            usn[2] = -Vr;
    ucs[3] = usn[1];        usn[3] = -ucs[1];

    // ---- window + pack + stage 0 from global ----
    const float* src = g_ident[layer] ? g_x[layer] : g_xm;
    const float2* xin2 = (const float2*)(src + (size_t)bc*NT);
    int ibase = f * (HOP/2);
    float zr[4], zi[4];
    #pragma unroll
    for (int u = 0; u < 4; u++) {
        int n = lt + u*256, gi = ibase + n;
        float2 v = (gi < NT/2) ? xin2[gi] : make_float2(0.f, 0.f);
        zr[u] = v.x * he[u];
        zi[u] = v.y * ho[u];
    }
    {
        float apcr = zr[0]+zr[2], apci = zi[0]+zi[2], amcr = zr[0]-zr[2], amci = zi[0]-zi[2];
        float bpdr = zr[1]+zr[3], bpdi = zi[1]+zi[3], bmdr = zr[1]-zr[3], bmdi = zi[1]-zi[3];
        float t1r = amcr + bmdi, t1i = amci - bmdr;
        float t3r = amcr - bmdi, t3i = amci + bmdr;
        float w2r = s0r*s0r - s0i*s0i, w2i = 2.0f*s0r*s0i;
        float w3r = w2r*s0r - w2i*s0i, w3i = w2r*s0i + w2i*s0r;
        float s2r = apcr - bpdr, s2i = apci - bpdi;
        int ob = 4*lt;
        AR[SKW(ob)]   = apcr + bpdr;         AI[SKW(ob)]   = apci + bpdi;
        AR[SKW(ob+1)] = t1r*s0r - t1i*s0i;   AI[SKW(ob+1)] = t1r*s0i + t1i*s0r;
        AR[SKW(ob+2)] = s2r*w2r - s2i*w2i;   AI[SKW(ob+2)] = s2r*w2i + s2i*w2r;
        AR[SKW(ob+3)] = t3r*w3r - t3i*w3i;   AI[SKW(ob+3)] = t3r*w3i + t3i*w3r;
    }
    __syncthreads();
    fwd_stage(AR, AI, BR, BI, lt,  4, 2, w1r_, w1i_);   // s=1
    __syncthreads();
    fwd_stage(BR, BI, AR, AI, lt, 16, 4, w2r_, w2i_);   // s=2
    __syncthreads();
    fwd_stage(AR, AI, BR, BI, lt, 64, 6, w3r_, w3i_);   // s=3
    __syncthreads();
    {   // stage 4: m=256, twiddle = 1, natural order out (ob = lt)
        float ar = BR[SKW(lt)],     ai = BI[SKW(lt)];
        float br = BR[SKW(lt+256)], bi = BI[SKW(lt+256)];
        float cr = BR[SKW(lt+512)], ci = BI[SKW(lt+512)];
        float dr = BR[SKW(lt+768)], di = BI[SKW(lt+768)];
        float apcr = ar+cr, apci = ai+ci, amcr = ar-cr, amci = ai-ci;
        float bpdr = br+dr, bpdi = bi+di, bmdr = br-dr, bmdi = bi-di;
        AR[SKW(lt)]     = apcr + bpdr;  AI[SKW(lt)]     = apci + bpdi;
        AR[SKW(lt+256)] = amcr + bmdi;  AI[SKW(lt+256)] = amci - bmdr;
        AR[SKW(lt+512)] = apcr - bpdr;  AI[SKW(lt+512)] = apci - bpdi;
        AR[SKW(lt+768)] = amcr - bmdi;  AI[SKW(lt+768)] = amci + bmdr;
    }
    __syncthreads();
    // ---- Hermitian unpack with register twiddles ----
    float2* out = g_spec + (size_t)(bc*FR + f)*KB;
    #pragma unroll
    for (int u = 0; u < 4; u++) {
        int k = lt + u*256;
        int kb = (NH - k) & (NH-1);
        float xr = AR[SKW(k)],  xi = AI[SKW(k)];
        float yr = AR[SKW(kb)], yi = -AI[SKW(kb)];
        float er  = 0.5f*(xr+yr), ei  = 0.5f*(xi+yi);
        float orr = 0.5f*(xr-yr), oii = 0.5f*(xi-yi);
        float wor = ucs[u]*orr - usn[u]*oii, woi = ucs[u]*oii + usn[u]*orr;
        out[k] = make_float2(er + woi, ei - wor);
    }
    if (lt == 0) {
        out[NH] = make_float2(AR[0] - AI[0], 0.f);
    }
}

// ---------------- chunk-boundary carries (MLP-8 batched loads) ----------------
__global__ void carry_kernel(int layer) {
    int idx = blockIdx.x * 256 + threadIdx.x;
    if (idx >= BC*KB) return;
    int bc = idx / KB, k = idx - bc*KB;
    int c = bc & (NC-1);
    float T = g_T[(size_t)(layer*NC + c)*KB + k];
    float2 cr = make_float2(0.f, 0.f);
    const float2* base = g_spec + (size_t)bc*FR*KB + k;
    for (int chb = 1; chb < CH; chb++) {
        float2 v[FPC];
        #pragma unroll
        for (int i = 0; i < FPC; i++)
            v[i] = base[(size_t)((chb-1)*FPC + i)*KB];
        #pragma unroll
        for (int i = 0; i < FPC; i++) {
            cr.x = (v[i].x + cr.x) * T;
            cr.y = (v[i].y + cr.y) * T;
        }
        g_carry[(size_t)chb*BC*KB + idx] = cr;
    }
}

// ---------------- inverse radix-4 stage, register twiddle (w = e^{+2pi i j/1024}) ----------------
__device__ __forceinline__ void inv_stage(const float* sR, const float* sI, float* dR, float* dI,
                                          int lt, int m, int l2m, float wr, float wi) {
    float ar = sR[SKW(lt)],     ai = sI[SKW(lt)];
    float br = sR[SKW(lt+256)], bi = sI[SKW(lt+256)];
    float cr = sR[SKW(lt+512)], ci = sI[SKW(lt+512)];
    float dr = sR[SKW(lt+768)], di = sI[SKW(lt+768)];
    float apcr = ar+cr, apci = ai+ci, amcr = ar-cr, amci = ai-ci;
    float bpdr = br+dr, bpdi = bi+di, bmdr = br-dr, bmdi = bi-di;
    float t1r = amcr - bmdi, t1i = amci + bmdr;
    float t3r = amcr + bmdi, t3i = amci - bmdr;
    float w2r = wr*wr - wi*wi, w2i = 2.0f*wr*wi;
    float w3r = w2r*wr - w2i*wi, w3i = w2r*wi + w2i*wr;
    int q  = lt & (m-1);
    int ob = q + ((lt >> l2m) << (l2m + 2));
    float s2r = apcr - bpdr, s2i = apci - bpdi;
    dR[SKW(ob)]      = apcr + bpdr;       dI[SKW(ob)]      = apci + bpdi;
    dR[SKW(ob+m)]    = t1r*wr - t1i*wi;   dI[SKW(ob+m)]    = t1r*wi + t1i*wr;
    dR[SKW(ob+2*m)]  = s2r*w2r - s2i*w2i; dI[SKW(ob+2*m)]  = s2r*w2i + s2i*w2r;
    dR[SKW(ob+3*m)]  = t3r*w3r - t3i*w3i; dI[SKW(ob+3*m)]  = t3r*w3i + t3i*w3r;
}

// ---------------- sweep: per (bc, chunk): scan + inverse FFT + window + OA + tanh ----------------
// OA tail in registers (same-thread); 5 barriers/frame; FPC=8 amortizes prologue.
__global__ void __launch_bounds__(256) sweep_kernel(int layer, const float* __restrict__ gains) {
    extern __shared__ float sm[];
    float2* X  = (float2*)sm;            // [KB] post-scan spectrum (mirror source)
    float*  AR = (float*)(X + KB);
    float*  AI = AR + SSZ;
    float*  BR = AI + SSZ;
    float*  BI = BR + SSZ;

    int blk = blockIdx.x;
    int bc = blk >> 4, ch = blk & (CH-1);
    int lt = threadIdx.x;
    int c = bc & (NC-1);
    float gain = gains[layer*NC + c];

    // ---- frame-invariant per-thread constants ----
    float s0r, s0i;
    sincospif((float)lt * (1.0f/512.0f), &s0i, &s0r);
    float w1r_, w1i_, w2r_, w2i_, w3r_, w3i_;
    { float sn, cs;
      sincospif((float)(lt & ~3)  * (1.0f/512.0f), &sn, &cs); w1r_ = cs; w1i_ = sn;
      sincospif((float)(lt & ~15) * (1.0f/512.0f), &sn, &cs); w2r_ = cs; w2i_ = sn;
      sincospif((float)(lt & ~63) * (1.0f/512.0f), &sn, &cs); w3r_ = cs; w3i_ = sn; }
    float Wr, Wi;
    { float sn, cs; sincospif((float)lt * (1.0f/1024.0f), &sn, &cs); Wr = cs; Wi = sn; }
    float co_, so_;
    { float sn, cs; sincospif((float)(2*lt+1) * (1.0f/1024.0f), &sn, &cs); co_ = cs; so_ = sn; }
    const float sc = 1.0f/(float)NH;
    float he[4], ho[4];
    he[0] = (0.5f - 0.5f*s0r)*sc; he[1] = (0.5f + 0.5f*s0i)*sc;
    he[2] = (0.5f + 0.5f*s0r)*sc; he[3] = (0.5f - 0.5f*s0i)*sc;
    ho[0] = (0.5f - 0.5f*co_)*sc; ho[1] = (0.5f + 0.5f*so_)*sc;
    ho[2] = (0.5f + 0.5f*co_)*sc; ho[3] = (0.5f - 0.5f*so_)*sc;
    const float RC = 0.70710678118654752f;
    float csu[4], snu[4];
    csu[0] = Wr;            snu[0] = Wi;
    csu[1] = RC*(Wr - Wi);  snu[1] = RC*(Wr + Wi);
    csu[2] = -Wi;           snu[2] = Wr;
    csu[3] = -snu[1];       snu[3] = csu[1];

    // scan registers
    float Treg[5]; float2 creg[5];
    #pragma unroll
    for (int u = 0; u < 5; u++) {
        int k = lt + u*256;
        if (k < KB) {
            Treg[u] = g_T[(size_t)(layer*NC + c)*KB + k];
            creg[u] = ch ? g_carry[(size_t)ch*BC*KB + (size_t)bc*KB + k] : make_float2(0.f, 0.f);
        }
    }

    const float2* specb = g_spec + (size_t)bc*FR*KB + (size_t)(ch*FPC)*KB;
    float* xout = g_x[layer+1] + (size_t)bc*NT;

    // OA tail registers (same-thread across frames): prev frame's ve2/vo2/ve3/vo3
    float pe2 = 0.f, po2 = 0.f, pe3 = 0.f, po3 = 0.f;

    // prefetch first frame
    float2 rv[5];
    #pragma unroll
    for (int u = 0; u < 5; u++) {
        int k = lt + u*256;
        if (k < KB) rv[u] = specb[k];
    }

    for (int fi = 0; fi < FPC; fi++) {
        int f = ch*FPC + fi;
        #pragma unroll
        for (int u = 0; u < 5; u++) {
            int k = lt + u*256;
            if (k < KB) {
                creg[u].x = (rv[u].x + creg[u].x) * Treg[u];
                creg[u].y = (rv[u].y + creg[u].y) * Treg[u];
                X[k] = creg[u];
            }
        }
        __syncthreads();
        if (fi + 1 < FPC) {
            const float2* sp = specb + (size_t)(fi+1)*KB;
            #pragma unroll
            for (int u = 0; u < 5; u++) {
                int k = lt + u*256;
                if (k < KB) rv[u] = sp[k];
            }
        }
        {
            float zr[4], zi[4];
            #pragma unroll
            for (int u = 0; u < 4; u++) {
                float2 Xa = creg[u];
                float2 Yc = X[NH - (lt + u*256)];
                float yr = Yc.x, yi = -Yc.y;
                float er  = 0.5f*(Xa.x+yr), ei  = 0.5f*(Xa.y+yi);
                float orr = 0.5f*(Xa.x-yr), oii = 0.5f*(Xa.y-yi);
                float wor = csu[u]*orr - snu[u]*oii, woi = csu[u]*oii + snu[u]*orr;
                zr[u] = er - woi;
                zi[u] = ei + wor;
            }
            float apcr = zr[0]+zr[2], apci = zi[0]+zi[2], amcr = zr[0]-zr[2], amci = zi[0]-zi[2];
            float bpdr = zr[1]+zr[3], bpdi = zi[1]+zi[3], bmdr = zr[1]-zr[3], bmdi = zi[1]-zi[3];
            float t1r = amcr - bmdi, t1i = amci + bmdr;
            float t3r = amcr + bmdi, t3i = amci - bmdr;
            float w2r = s0r*s0r - s0i*s0i, w2i = 2.0f*s0r*s0i;
            float w3r = w2r*s0r - w2i*s0i, w3i = w2r*s0i + w2i*s0r;
            float s2r = apcr - bpdr, s2i = apci - bpdi;
            int ob = 4*lt;
            AR[SKW(ob)]   = apcr + bpdr;           AI[SKW(ob)]   = apci + bpdi;
            AR[SKW(ob+1)] = t1r*s0r - t1i*s0i;     AI[SKW(ob+1)] = t1r*s0i + t1i*s0r;
            AR[SKW(ob+2)] = s2r*w2r - s2i*w2i;     AI[SKW(ob+2)] = s2r*w2i + s2i*w2r;
            AR[SKW(ob+3)] = t3r*w3r - t3i*w3i;     AI[SKW(ob+3)] = t3r*w3i + t3i*w3r;
        }
        __syncthreads();
        inv_stage(AR, AI, BR, BI, lt,  4, 2, w1r_, w1i_);
        __syncthreads();
        inv_stage(BR, BI, AR, AI, lt, 16, 4, w2r_, w2i_);
        __syncthreads();
        inv_stage(AR, AI, BR, BI, lt, 64, 6, w3r_, w3i_);
        __syncthreads();
        float y0r, y0i, y1r, y1i, y2r, y2i, y3r, y3i;
        {
            float ar = BR[SKW(lt)],     ai = BI[SKW(lt)];
            float br = BR[SKW(lt+256)], bi = BI[SKW(lt+256)];
            float cr = BR[SKW(lt+512)], ci = BI[SKW(lt+512)];
            float dr = BR[SKW(lt+768)], di = BI[SKW(lt+768)];
            float apcr = ar+cr, apci = ai+ci, amcr = ar-cr, amci = ai-ci;
            float bpdr = br+dr, bpdi = bi+di, bmdr = br-dr, bmdi = bi-di;
            y0r = apcr + bpdr; y0i = apci + bpdi;
            y1r = amcr - bmdi; y1i = amci + bmdr;
            y2r = apcr - bpdr; y2i = apci - bpdi;
            y3r = amcr + bmdi; y3i = amci - bmdr;
        }
        float ve0 = y0r*he[0], vo0 = y0i*ho[0];
        float ve1 = y1r*he[1], vo1 = y1i*ho[1];
        float ve2 = y2r*he[2], vo2 = y2i*ho[2];
        float ve3 = y3r*he[3], vo3 = y3i*ho[3];
        if (fi > 0) {
            float2* out2 = (float2*)xout + (size_t)f*512;
            out2[lt]       = make_float2(tanhf(gain*(pe2 + ve0)), tanhf(gain*(po2 + vo0)));
            out2[lt + 256] = make_float2(tanhf(gain*(pe3 + ve1)), tanhf(gain*(po3 + vo1)));
        } else {
            float2* bf = g_bnd_first + (size_t)(bc*CH + ch)*512;
            bf[lt]       = make_float2(ve0, vo0);
            bf[lt + 256] = make_float2(ve1, vo1);
        }
        pe2 = ve2; po2 = vo2; pe3 = ve3; po3 = vo3;
        if (fi == FPC-1) {
            float2* bs = g_bnd_sec + (size_t)(bc*CH + ch)*512;
            bs[lt]       = make_float2(ve2, vo2);
            bs[lt + 256] = make_float2(ve3, vo3);
        }
        // no trailing barrier: A/B smem ping-pong + top-of-loop barrier provide ordering
    }
}

// ---------------- stitch: chunk-boundary segments ----------------
__global__ void stitch_kernel(int layer, const float* __restrict__ gains) {
    int idx = blockIdx.x * 256 + threadIdx.x;       // float2 index over BC*CH*512
    if (idx >= BC*CH*512) return;
    int bc = idx / (CH*512);
    int r  = idx - bc*(CH*512);
    int ch = r >> 9, m = r & 511;
    int c = bc & (NC-1);
    float g = gains[layer*NC + c];
    float2 fv = g_bnd_first[idx];
    float2 sv = make_float2(0.f, 0.f);
    if (ch > 0) sv = g_bnd_sec[(size_t)(bc*CH + ch - 1)*512 + m];
    float2 o = make_float2(tanhf(g*(fv.x + sv.x)), tanhf(g*(fv.y + sv.y)));
    ((float2*)(g_x[layer+1] + (size_t)bc*NT))[(size_t)ch*FPC*512 + m] = o;
}

// ---------------- softmax layer mix + channel sum (float4) ----------------
__global__ void final_kernel(const float* __restrict__ mixer, float* __restrict__ out) {
    int idx = blockIdx.x * 256 + threadIdx.x;
    if (idx >= NB*NT/4) return;
    int b = idx / (NT/4), t4 = idx - b*(NT/4);
    float m0 = mixer[0], m1 = mixer[1], m2 = mixer[2], m3 = mixer[3];
    float mx = fmaxf(fmaxf(m0, m1), fmaxf(m2, m3));
    float e0 = expf(m0-mx), e1 = expf(m1-mx), e2 = expf(m2-mx), e3 = expf(m3-mx);
    float inv = 1.0f / (e0+e1+e2+e3);
    float w[4] = {e0*inv, e1*inv, e2*inv, e3*inv};
    float4 acc = make_float4(0.f,0.f,0.f,0.f);
    for (int c = 0; c < NC; c++) {
        size_t off4 = (size_t)(b*NC + c)*(NT/4) + t4;
        #pragma unroll
        for (int l = 0; l < 4; l++) {
            float4 v = ((const float4*)g_x[l])[off4];
            acc.x += w[l]*v.x; acc.y += w[l]*v.y; acc.z += w[l]*v.z; acc.w += w[l]*v.w;
        }
    }
    ((float4*)out)[idx] = acc;
}

// ---------------- sig passthrough ----------------
__global__ void copy_sig_kernel(const float* __restrict__ sig, float* __restrict__ out) {
    int i = blockIdx.x * 256 + threadIdx.x;
    if (i < NB*NC*NFR) out[NB*NT + i] = sig[i];
}

// ---------------- launch ----------------
extern "C" void kernel_launch(void* const* d_in, const int* in_sizes, int n_in,
                              void* d_out, int out_size) {
    const float* sig        = (const float*)d_in[0];
    const float* noise      = (const float*)d_in[1];
    const float* decays     = (const float*)d_in[2];
    const float* mixer      = (const float*)d_in[3];
    const float* transfers  = (const float*)d_in[4];
    const float* mixer_mats = (const float*)d_in[5];
    const float* gains      = (const float*)d_in[6];
    const float* fb         = (const float*)d_in[7];
    float* out = (float*)d_out;

    cudaFuncSetAttribute(sweep_kernel, cudaFuncAttributeMaxDynamicSharedMemorySize, SWEEP_BYTES);

    init_kernel<<<64, 256>>>(decays);
    ident_kernel<<<NL, 256>>>(mixer_mats);
    tmat_kernel<<<NL*NC, 256>>>(transfers, fb);
    x0_kernel<<<(BC*NT/4 + 255)/256, 256>>>(sig, noise);

    for (int l = 0; l < NL; l++) {
        dim3 mg(NT/256, NB);
        mix_kernel<<<mg, 256>>>(l, mixer_mats + l*NC*NC);   // early-exits when identity
        fwd_kernel<<<BC*FR, 256>>>(l);
        carry_kernel<<<(BC*KB + 255)/256, 256>>>(l);
        sweep_kernel<<<BC*CH, 256, SWEEP_BYTES>>>(l, gains);
        stitch_kernel<<<(BC*CH*512 + 255)/256, 256>>>(l, gains);
    }

    final_kernel<<<(NB*NT/4 + 255)/256, 256>>>(mixer, out);
    if (out_size >= NB*NT + NB*NC*NFR)
        copy_sig_kernel<<<(NB*NC*NFR + 255)/256, 256>>>(sig, out);
}

// round 17
// speedup vs baseline: 1.0044x; 1.0044x over previous
#include <cuda_runtime.h>
#include <math.h>

// ---------------- problem constants ----------------
#define NB 4            // batch
#define NC 32           // channels
#define NT 131072       // samples
#define NFR 256         // sig frames
#define SPF 512         // samples per sig frame
#define WS 2048         // window size
#define HOP 1024        // step
#define FR 128          // fft frames per signal
#define KB 1025         // rfft bins
#define BC (NB*NC)      // 128
#define NL 3            // layers
#define NH 1024         // complex FFT length (real 2048 packed)
#define CH 16           // chunks per signal
#define FPC 8           // frames per chunk

// skewed smem indexing: conflict-free for stride-4m scatter stores
#define SKW(i) ((i) + ((i) >> 5))
#define SSZ (NH + (NH >> 5) + 1)   // 1057

// sweep kernel dynamic smem (floats): float2 X[KB]; float AR,AI,BR,BI[SSZ]; prevsec[2][1024]
#define SWEEP_FLOATS (2*KB + 4*SSZ + 2048)
#define SWEEP_BYTES (SWEEP_FLOATS * 4)

// ---------------- device scratch (static: no runtime allocation) ----------------
__device__ float  g_env[NC*SPF];
__device__ float  g_T[NL*NC*KB];
__device__ float  g_x[NL+1][BC*NT];
__device__ float  g_xm[BC*NT];
__device__ float2 g_spec[BC*FR*KB];          // spectra
__device__ float2 g_carry[CH*BC*KB];         // chunk-entry carries (ch=0 unused)
__device__ float2 g_bnd_first[BC*CH*512];    // chunk-first-frame first half (pairs)
__device__ float2 g_bnd_sec[BC*CH*512];      // chunk-last-frame second half (pairs)
__device__ int    g_ident[NL];

// ---------------- init: envelopes ----------------
__global__ void init_kernel(const float* __restrict__ decays) {
    int tid = blockIdx.x * blockDim.x + threadIdx.x;
    if (tid < NC*SPF) {
        int ch = tid / SPF, j = tid - ch*SPF;
        float base = (float)(SPF-1 - j) * (1.0f/(float)(SPF-1));
        g_env[tid] = powf(base, decays[ch]);
    }
}

// ---------------- identity check for mixer matrices ----------------
__global__ void ident_kernel(const float* __restrict__ M) {
    __shared__ int ok;
    if (threadIdx.x == 0) ok = 1;
    __syncthreads();
    const float* m = M + blockIdx.x * NC*NC;
    for (int i = threadIdx.x; i < NC*NC; i += 256) {
        float expect = ((i / NC) == (i % NC)) ? 1.0f : 0.0f;
        if (m[i] != expect) atomicExch(&ok, 0);
    }
    __syncthreads();
    if (threadIdx.x == 0) g_ident[blockIdx.x] = ok;
}

// ---------------- T = transfers @ filter_bank (exploit ~1% sparsity) ----------------
__global__ void tmat_kernel(const float* __restrict__ transfers, const float* __restrict__ fb) {
    int lc  = blockIdx.x;
    int tid = threadIdx.x;
    const float* tr = transfers + (size_t)lc * KB;
    float acc[5] = {0.f,0.f,0.f,0.f,0.f};
    for (int j = 0; j < KB; j++) {
        float t = tr[j];
        if (t != 0.0f) {
            const float* row = fb + (size_t)j * KB;
            #pragma unroll
            for (int u = 0; u < 5; u++) {
                int k = tid + u*256;
                if (k < KB) acc[u] += t * row[k];
            }
        }
    }
    #pragma unroll
    for (int u = 0; u < 5; u++) {
        int k = tid + u*256;
        if (k < KB) g_T[(size_t)lc*KB + k] = acc[u];
    }
}

// ---------------- excitation (float4) ----------------
__global__ void x0_kernel(const float* __restrict__ sig, const float* __restrict__ noise) {
    int idx = blockIdx.x * 256 + threadIdx.x;       // float4 index
    if (idx >= BC*NT/4) return;
    int bc = idx / (NT/4), t4 = idx - bc*(NT/4);
    int t  = t4 * 4;
    int c = bc & (NC-1);
    int f = t >> 9, j = t & 511;
    float s = sig[bc*NFR + f];
    float4 nz = ((const float4*)noise)[t4];
    float4 ev = ((const float4*)g_env)[c*(SPF/4) + (j >> 2)];
    float4 o;
    o.x = s * ev.x * nz.x;  o.y = s * ev.y * nz.y;
    o.z = s * ev.z * nz.z;  o.w = s * ev.w * nz.w;
    ((float4*)(g_x[0] + (size_t)bc*NT))[t4] = o;
}

// ---------------- channel mixing (only runs when mixer_mat != identity) ----------------
__global__ void __launch_bounds__(256) mix_kernel(int layer, const float* __restrict__ M) {
    if (g_ident[layer]) return;
    __shared__ float Ms[NC*NC];
    int b = blockIdx.y, t = blockIdx.x * 256 + threadIdx.x;
    for (int i = threadIdx.x; i < NC*NC; i += 256) Ms[i] = M[i];
    __syncthreads();
    const float* xin = g_x[layer] + (size_t)b*NC*NT + t;
    float xv[NC];
    #pragma unroll
    for (int c = 0; c < NC; c++) xv[c] = xin[(size_t)c*NT];
    float* xo = g_xm + (size_t)b*NC*NT + t;
    #pragma unroll
    for (int d = 0; d < NC; d++) {
        float s = 0.f;
        #pragma unroll
        for (int c = 0; c < NC; c++) s += xv[c] * Ms[c*NC + d];
        xo[(size_t)d*NT] = s;
    }
}

// ---------------- forward radix-4 stage, register twiddle (w = e^{-2pi i j/1024}) ----------------
__device__ __forceinline__ void fwd_stage(const float* sR, const float* sI, float* dR, float* dI,
                                          int lt, int m, int l2m, float wr, float wi) {
    float ar = sR[SKW(lt)],     ai = sI[SKW(lt)];
    float br = sR[SKW(lt+256)], bi = sI[SKW(lt+256)];
    float cr = sR[SKW(lt+512)], ci = sI[SKW(lt+512)];
    float dr = sR[SKW(lt+768)], di = sI[SKW(lt+768)];
    float apcr = ar+cr, apci = ai+ci, amcr = ar-cr, amci = ai-ci;
    float bpdr = br+dr, bpdi = bi+di, bmdr = br-dr, bmdi = bi-di;
    float t1r = amcr + bmdi, t1i = amci - bmdr;
    float t3r = amcr - bmdi, t3i = amci + bmdr;
    float w2r = wr*wr - wi*wi, w2i = 2.0f*wr*wi;
    float w3r = w2r*wr - w2i*wi, w3i = w2r*wi + w2i*wr;
    int q  = lt & (m-1);
    int ob = q + ((lt >> l2m) << (l2m + 2));
    float s2r = apcr - bpdr, s2i = apci - bpdi;
    dR[SKW(ob)]      = apcr + bpdr;       dI[SKW(ob)]      = apci + bpdi;
    dR[SKW(ob+m)]    = t1r*wr - t1i*wi;   dI[SKW(ob+m)]    = t1r*wi + t1i*wr;
    dR[SKW(ob+2*m)]  = s2r*w2r - s2i*w2i; dI[SKW(ob+2*m)]  = s2r*w2i + s2i*w2r;
    dR[SKW(ob+3*m)]  = t3r*w3r - t3i*w3i; dI[SKW(ob+3*m)]  = t3r*w3i + t3i*w3r;
}

// ---------------- forward FFT: one frame per block, all-register twiddles ----------------
__global__ void __launch_bounds__(256) fwd_kernel(int layer) {
    __shared__ float AR[SSZ], AI[SSZ], BR[SSZ], BI[SSZ];
    int blk = blockIdx.x, bc = blk >> 7, f = blk & (FR-1), lt = threadIdx.x;

    // ---- frame-invariant per-thread constants ----
    float cs_, sn_;                        // (cos,sin)(pi lt/512)
    sincospif((float)lt * (1.0f/512.0f), &sn_, &cs_);
    float s0r = cs_, s0i = -sn_;           // stage0 twiddle e^{-2pi i lt/1024}
    float w1r_, w1i_, w2r_, w2i_, w3r_, w3i_;
    { float sn, cs;
      sincospif(-(float)(lt & ~3)  * (1.0f/512.0f), &sn, &cs); w1r_ = cs; w1i_ = sn;
      sincospif(-(float)(lt & ~15) * (1.0f/512.0f), &sn, &cs); w2r_ = cs; w2i_ = sn;
      sincospif(-(float)(lt & ~63) * (1.0f/512.0f), &sn, &cs); w3r_ = cs; w3i_ = sn; }
    float he[4], ho[4];                    // hann at samples 2n / 2n+1, n = lt+256u
    he[0] = 0.5f - 0.5f*cs_; he[1] = 0.5f + 0.5f*sn_;
    he[2] = 0.5f + 0.5f*cs_; he[3] = 0.5f - 0.5f*sn_;
    { float sn, cs; sincospif((float)(2*lt+1) * (1.0f/1024.0f), &sn, &cs);
      ho[0] = 0.5f - 0.5f*cs; ho[1] = 0.5f + 0.5f*sn;
      ho[2] = 0.5f + 0.5f*cs; ho[3] = 0.5f - 0.5f*sn; }
    // unpack rotation e^{-i pi k/1024}, k = lt+256u: V * e^{-i pi u/4}
    const float RC = 0.70710678118654752f;
    float Vr, Vi;
    { float sn, cs; sincospif((float)lt * (1.0f/1024.0f), &sn, &cs); Vr = cs; Vi = -sn; }
    float ucs[4], usn[4];
    ucs[0] = Vr;            usn[0] = Vi;
    ucs[1] = RC*(Vr + Vi);  usn[1] = RC*(Vi - Vr);
    ucs[2] = Vi;            usn[2] = -Vr;
    ucs[3] = usn[1];        usn[3] = -ucs[1];

    // ---- window + pack + stage 0 from global ----
    const float* src = g_ident[layer] ? g_x[layer] : g_xm;
    const float2* xin2 = (const float2*)(src + (size_t)bc*NT);
    int ibase = f * (HOP/2);
    float zr[4], zi[4];
    #pragma unroll
    for (int u = 0; u < 4; u++) {
        int n = lt + u*256, gi = ibase + n;
        float2 v = (gi < NT/2) ? xin2[gi] : make_float2(0.f, 0.f);
        zr[u] = v.x * he[u];
        zi[u] = v.y * ho[u];
    }
    {
        float apcr = zr[0]+zr[2], apci = zi[0]+zi[2], amcr = zr[0]-zr[2], amci = zi[0]-zi[2];
        float bpdr = zr[1]+zr[3], bpdi = zi[1]+zi[3], bmdr = zr[1]-zr[3], bmdi = zi[1]-zi[3];
        float t1r = amcr + bmdi, t1i = amci - bmdr;
        float t3r = amcr - bmdi, t3i = amci + bmdr;
        float w2r = s0r*s0r - s0i*s0i, w2i = 2.0f*s0r*s0i;
        float w3r = w2r*s0r - w2i*s0i, w3i = w2r*s0i + w2i*s0r;
        float s2r = apcr - bpdr, s2i = apci - bpdi;
        int ob = 4*lt;
        AR[SKW(ob)]   = apcr + bpdr;         AI[SKW(ob)]   = apci + bpdi;
        AR[SKW(ob+1)] = t1r*s0r - t1i*s0i;   AI[SKW(ob+1)] = t1r*s0i + t1i*s0r;
        AR[SKW(ob+2)] = s2r*w2r - s2i*w2i;   AI[SKW(ob+2)] = s2r*w2i + s2i*w2r;
        AR[SKW(ob+3)] = t3r*w3r - t3i*w3i;   AI[SKW(ob+3)] = t3r*w3i + t3i*w3r;
    }
    __syncthreads();
    fwd_stage(AR, AI, BR, BI, lt,  4, 2, w1r_, w1i_);   // s=1
    __syncthreads();
    fwd_stage(BR, BI, AR, AI, lt, 16, 4, w2r_, w2i_);   // s=2
    __syncthreads();
    fwd_stage(AR, AI, BR, BI, lt, 64, 6, w3r_, w3i_);   // s=3
    __syncthreads();
    {   // stage 4: m=256, twiddle = 1, natural order out (ob = lt)
        float ar = BR[SKW(lt)],     ai = BI[SKW(lt)];
        float br = BR[SKW(lt+256)], bi = BI[SKW(lt+256)];
        float cr = BR[SKW(lt+512)], ci = BI[SKW(lt+512)];
        float dr = BR[SKW(lt+768)], di = BI[SKW(lt+768)];
        float apcr = ar+cr, apci = ai+ci, amcr = ar-cr, amci = ai-ci;
        float bpdr = br+dr, bpdi = bi+di, bmdr = br-dr, bmdi = bi-di;
        AR[SKW(lt)]     = apcr + bpdr;  AI[SKW(lt)]     = apci + bpdi;
        AR[SKW(lt+256)] = amcr + bmdi;  AI[SKW(lt+256)] = amci - bmdr;
        AR[SKW(lt+512)] = apcr - bpdr;  AI[SKW(lt+512)] = apci - bpdi;
        AR[SKW(lt+768)] = amcr - bmdi;  AI[SKW(lt+768)] = amci + bmdr;
    }
    __syncthreads();
    // ---- Hermitian unpack with register twiddles ----
    float2* out = g_spec + (size_t)(bc*FR + f)*KB;
    #pragma unroll
    for (int u = 0; u < 4; u++) {
        int k = lt + u*256;
        int kb = (NH - k) & (NH-1);
        float xr = AR[SKW(k)],  xi = AI[SKW(k)];
        float yr = AR[SKW(kb)], yi = -AI[SKW(kb)];
        float er  = 0.5f*(xr+yr), ei  = 0.5f*(xi+yi);
        float orr = 0.5f*(xr-yr), oii = 0.5f*(xi-yi);
        float wor = ucs[u]*orr - usn[u]*oii, woi = ucs[u]*oii + usn[u]*orr;
        out[k] = make_float2(er + woi, ei - wor);
    }
    if (lt == 0) {
        out[NH] = make_float2(AR[0] - AI[0], 0.f);
    }
}

// ---------------- chunk-boundary carries (MLP-8 batched loads) ----------------
__global__ void carry_kernel(int layer) {
    int idx = blockIdx.x * 256 + threadIdx.x;
    if (idx >= BC*KB) return;
    int bc = idx / KB, k = idx - bc*KB;
    int c = bc & (NC-1);
    float T = g_T[(size_t)(layer*NC + c)*KB + k];
    float2 cr = make_float2(0.f, 0.f);
    const float2* base = g_spec + (size_t)bc*FR*KB + k;
    for (int chb = 1; chb < CH; chb++) {
        float2 v[FPC];
        #pragma unroll
        for (int i = 0; i < FPC; i++)
            v[i] = base[(size_t)((chb-1)*FPC + i)*KB];
        #pragma unroll
        for (int i = 0; i < FPC; i++) {
            cr.x = (v[i].x + cr.x) * T;
            cr.y = (v[i].y + cr.y) * T;
        }
        g_carry[(size_t)chb*BC*KB + idx] = cr;
    }
}

// ---------------- inverse radix-4 stage, register twiddle (w = e^{+2pi i j/1024}) ----------------
__device__ __forceinline__ void inv_stage(const float* sR, const float* sI, float* dR, float* dI,
                                          int lt, int m, int l2m, float wr, float wi) {
    float ar = sR[SKW(lt)],     ai = sI[SKW(lt)];
    float br = sR[SKW(lt+256)], bi = sI[SKW(lt+256)];
    float cr = sR[SKW(lt+512)], ci = sI[SKW(lt+512)];
    float dr = sR[SKW(lt+768)], di = sI[SKW(lt+768)];
    float apcr = ar+cr, apci = ai+ci, amcr = ar-cr, amci = ai-ci;
    float bpdr = br+dr, bpdi = bi+di, bmdr = br-dr, bmdi = bi-di;
    float t1r = amcr - bmdi, t1i = amci + bmdr;
    float t3r = amcr + bmdi, t3i = amci - bmdr;
    float w2r = wr*wr - wi*wi, w2i = 2.0f*wr*wi;
    float w3r = w2r*wr - w2i*wi, w3i = w2r*wi + w2i*wr;
    int q  = lt & (m-1);
    int ob = q + ((lt >> l2m) << (l2m + 2));
    float s2r = apcr - bpdr, s2i = apci - bpdi;
    dR[SKW(ob)]      = apcr + bpdr;       dI[SKW(ob)]      = apci + bpdi;
    dR[SKW(ob+m)]    = t1r*wr - t1i*wi;   dI[SKW(ob+m)]    = t1r*wi + t1i*wr;
    dR[SKW(ob+2*m)]  = s2r*w2r - s2i*w2i; dI[SKW(ob+2*m)]  = s2r*w2i + s2i*w2r;
    dR[SKW(ob+3*m)]  = t3r*w3r - t3i*w3i; dI[SKW(ob+3*m)]  = t3r*w3i + t3i*w3r;
}

// ---------------- sweep: per (bc, chunk): scan + inverse FFT + window + OA + tanh ----------------
// R13 form (measured 713.5): prevsec smem double-buffer, 6 barriers/frame.
__global__ void __launch_bounds__(256) sweep_kernel(int layer, const float* __restrict__ gains) {
    extern __shared__ float sm[];
    float2* X  = (float2*)sm;            // [KB] post-scan spectrum (mirror source)
    float*  AR = (float*)(X + KB);
    float*  AI = AR + SSZ;
    float*  BR = AI + SSZ;
    float*  BI = BR + SSZ;
    float*  prevsec = BI + SSZ;          // [2][1024]

    int blk = blockIdx.x;
    int bc = blk >> 4, ch = blk & (CH-1);
    int lt = threadIdx.x;
    int c = bc & (NC-1);
    float gain = gains[layer*NC + c];

    // ---- frame-invariant per-thread constants ----
    float s0r, s0i;
    sincospif((float)lt * (1.0f/512.0f), &s0i, &s0r);
    float w1r_, w1i_, w2r_, w2i_, w3r_, w3i_;
    { float sn, cs;
      sincospif((float)(lt & ~3)  * (1.0f/512.0f), &sn, &cs); w1r_ = cs; w1i_ = sn;
      sincospif((float)(lt & ~15) * (1.0f/512.0f), &sn, &cs); w2r_ = cs; w2i_ = sn;
      sincospif((float)(lt & ~63) * (1.0f/512.0f), &sn, &cs); w3r_ = cs; w3i_ = sn; }
    float Wr, Wi;
    { float sn, cs; sincospif((float)lt * (1.0f/1024.0f), &sn, &cs); Wr = cs; Wi = sn; }
    float co_, so_;
    { float sn, cs; sincospif((float)(2*lt+1) * (1.0f/1024.0f), &sn, &cs); co_ = cs; so_ = sn; }
    const float sc = 1.0f/(float)NH;
    float he[4], ho[4];
    he[0] = (0.5f - 0.5f*s0r)*sc; he[1] = (0.5f + 0.5f*s0i)*sc;
    he[2] = (0.5f + 0.5f*s0r)*sc; he[3] = (0.5f - 0.5f*s0i)*sc;
    ho[0] = (0.5f - 0.5f*co_)*sc; ho[1] = (0.5f + 0.5f*so_)*sc;
    ho[2] = (0.5f + 0.5f*co_)*sc; ho[3] = (0.5f - 0.5f*so_)*sc;
    const float RC = 0.70710678118654752f;
    float csu[4], snu[4];
    csu[0] = Wr;            snu[0] = Wi;
    csu[1] = RC*(Wr - Wi);  snu[1] = RC*(Wr + Wi);
    csu[2] = -Wi;           snu[2] = Wr;
    csu[3] = -snu[1];       snu[3] = csu[1];

    // scan registers
    float Treg[5]; float2 creg[5];
    #pragma unroll
    for (int u = 0; u < 5; u++) {
        int k = lt + u*256;
        if (k < KB) {
            Treg[u] = g_T[(size_t)(layer*NC + c)*KB + k];
            creg[u] = ch ? g_carry[(size_t)ch*BC*KB + (size_t)bc*KB + k] : make_float2(0.f, 0.f);
        }
    }

    const float2* specb = g_spec + (size_t)bc*FR*KB + (size_t)(ch*FPC)*KB;
    float* xout = g_x[layer+1] + (size_t)bc*NT;

    // prefetch first frame
    float2 rv[5];
    #pragma unroll
    for (int u = 0; u < 5; u++) {
        int k = lt + u*256;
        if (k < KB) rv[u] = specb[k];
    }

    for (int fi = 0; fi < FPC; fi++) {
        int f = ch*FPC + fi;
        #pragma unroll
        for (int u = 0; u < 5; u++) {
            int k = lt + u*256;
            if (k < KB) {
                creg[u].x = (rv[u].x + creg[u].x) * Treg[u];
                creg[u].y = (rv[u].y + creg[u].y) * Treg[u];
                X[k] = creg[u];
            }
        }
        __syncthreads();
        if (fi + 1 < FPC) {
            const float2* sp = specb + (size_t)(fi+1)*KB;
            #pragma unroll
            for (int u = 0; u < 5; u++) {
                int k = lt + u*256;
                if (k < KB) rv[u] = sp[k];
            }
        }
        {
            float zr[4], zi[4];
            #pragma unroll
            for (int u = 0; u < 4; u++) {
                float2 Xa = creg[u];
                float2 Yc = X[NH - (lt + u*256)];
                float yr = Yc.x, yi = -Yc.y;
                float er  = 0.5f*(Xa.x+yr), ei  = 0.5f*(Xa.y+yi);
                float orr = 0.5f*(Xa.x-yr), oii = 0.5f*(Xa.y-yi);
                float wor = csu[u]*orr - snu[u]*oii, woi = csu[u]*oii + snu[u]*orr;
                zr[u] = er - woi;
                zi[u] = ei + wor;
            }
            float apcr = zr[0]+zr[2], apci = zi[0]+zi[2], amcr = zr[0]-zr[2], amci = zi[0]-zi[2];
            float bpdr = zr[1]+zr[3], bpdi = zi[1]+zi[3], bmdr = zr[1]-zr[3], bmdi = zi[1]-zi[3];
            float t1r = amcr - bmdi, t1i = amci + bmdr;
            float t3r = amcr + bmdi, t3i = amci - bmdr;
            float w2r = s0r*s0r - s0i*s0i, w2i = 2.0f*s0r*s0i;
            float w3r = w2r*s0r - w2i*s0i, w3i = w2r*s0i + w2i*s0r;
            float s2r = apcr - bpdr, s2i = apci - bpdi;
            int ob = 4*lt;
            AR[SKW(ob)]   = apcr + bpdr;           AI[SKW(ob)]   = apci + bpdi;
            AR[SKW(ob+1)] = t1r*s0r - t1i*s0i;     AI[SKW(ob+1)] = t1r*s0i + t1i*s0r;
            AR[SKW(ob+2)] = s2r*w2r - s2i*w2i;     AI[SKW(ob+2)] = s2r*w2i + s2i*w2r;
            AR[SKW(ob+3)] = t3r*w3r - t3i*w3i;     AI[SKW(ob+3)] = t3r*w3i + t3i*w3r;
        }
        __syncthreads();
        inv_stage(AR, AI, BR, BI, lt,  4, 2, w1r_, w1i_);
        __syncthreads();
        inv_stage(BR, BI, AR, AI, lt, 16, 4, w2r_, w2i_);
        __syncthreads();
        inv_stage(AR, AI, BR, BI, lt, 64, 6, w3r_, w3i_);
        __syncthreads();
        float y0r, y0i, y1r, y1i, y2r, y2i, y3r, y3i;
        {
            float ar = BR[SKW(lt)],     ai = BI[SKW(lt)];
            float br = BR[SKW(lt+256)], bi = BI[SKW(lt+256)];
            float cr = BR[SKW(lt+512)], ci = BI[SKW(lt+512)];
            float dr = BR[SKW(lt+768)], di = BI[SKW(lt+768)];
            float apcr = ar+cr, apci = ai+ci, amcr = ar-cr, amci = ai-ci;
            float bpdr = br+dr, bpdi = bi+di, bmdr = br-dr, bmdi = bi-di;
            y0r = apcr + bpdr; y0i = apci + bpdi;
            y1r = amcr - bmdi; y1i = amci + bmdr;
            y2r = apcr - bpdr; y2i = apci - bpdi;
            y3r = amcr + bmdi; y3i = amci - bmdr;
        }
        float ve[4] = { y0r*he[0], y1r*he[1], y2r*he[2], y3r*he[3] };
        float vo[4] = { y0i*ho[0], y1i*ho[1], y2i*ho[2], y3i*ho[3] };
        float* rd = prevsec + (fi & 1)*1024;
        float* wr = prevsec + ((fi+1) & 1)*1024;
        if (fi > 0) {
            float2* out2 = (float2*)xout + (size_t)f*512;
            #pragma unroll
            for (int u = 0; u < 2; u++) {
                int n = lt + u*256;
                float a0 = rd[2*n]   + ve[u];
                float a1 = rd[2*n+1] + vo[u];
                out2[n] = make_float2(tanhf(gain*a0), tanhf(gain*a1));
            }
        } else {
            float2* bf = g_bnd_first + (size_t)(bc*CH + ch)*512;
            #pragma unroll
            for (int u = 0; u < 2; u++) {
                int n = lt + u*256;
                bf[n] = make_float2(ve[u], vo[u]);
            }
        }
        #pragma unroll
        for (int u = 2; u < 4; u++) {
            int n = lt + u*256;
            int j2 = 2*(n - 512);
            wr[j2]   = ve[u];
            wr[j2+1] = vo[u];
        }
        if (fi == FPC-1) {
            float2* bs = g_bnd_sec + (size_t)(bc*CH + ch)*512;
            #pragma unroll
            for (int u = 2; u < 4; u++) {
                int n = lt + u*256;
                bs[n - 512] = make_float2(ve[u], vo[u]);
            }
        }
        __syncthreads();
    }
}

// ---------------- stitch: chunk-boundary segments ----------------
__global__ void stitch_kernel(int layer, const float* __restrict__ gains) {
    int idx = blockIdx.x * 256 + threadIdx.x;       // float2 index over BC*CH*512
    if (idx >= BC*CH*512) return;
    int bc = idx / (CH*512);
    int r  = idx - bc*(CH*512);
    int ch = r >> 9, m = r & 511;
    int c = bc & (NC-1);
    float g = gains[layer*NC + c];
    float2 fv = g_bnd_first[idx];
    float2 sv = make_float2(0.f, 0.f);
    if (ch > 0) sv = g_bnd_sec[(size_t)(bc*CH + ch - 1)*512 + m];
    float2 o = make_float2(tanhf(g*(fv.x + sv.x)), tanhf(g*(fv.y + sv.y)));
    ((float2*)(g_x[layer+1] + (size_t)bc*NT))[(size_t)ch*FPC*512 + m] = o;
}

// ---------------- softmax layer mix + channel sum (float4) ----------------
__global__ void final_kernel(const float* __restrict__ mixer, float* __restrict__ out) {
    int idx = blockIdx.x * 256 + threadIdx.x;
    if (idx >= NB*NT/4) return;
    int b = idx / (NT/4), t4 = idx - b*(NT/4);
    float m0 = mixer[0], m1 = mixer[1], m2 = mixer[2], m3 = mixer[3];
    float mx = fmaxf(fmaxf(m0, m1), fmaxf(m2, m3));
    float e0 = expf(m0-mx), e1 = expf(m1-mx), e2 = expf(m2-mx), e3 = expf(m3-mx);
    float inv = 1.0f / (e0+e1+e2+e3);
    float w[4] = {e0*inv, e1*inv, e2*inv, e3*inv};
    float4 acc = make_float4(0.f,0.f,0.f,0.f);
    for (int c = 0; c < NC; c++) {
        size_t off4 = (size_t)(b*NC + c)*(NT/4) + t4;
        #pragma unroll
        for (int l = 0; l < 4; l++) {
            float4 v = ((const float4*)g_x[l])[off4];
            acc.x += w[l]*v.x; acc.y += w[l]*v.y; acc.z += w[l]*v.z; acc.w += w[l]*v.w;
        }
    }
    ((float4*)out)[idx] = acc;
}

// ---------------- sig passthrough ----------------
__global__ void copy_sig_kernel(const float* __restrict__ sig, float* __restrict__ out) {
    int i = blockIdx.x * 256 + threadIdx.x;
    if (i < NB*NC*NFR) out[NB*NT + i] = sig[i];
}

// ---------------- launch ----------------
extern "C" void kernel_launch(void* const* d_in, const int* in_sizes, int n_in,
                              void* d_out, int out_size) {
    const float* sig        = (const float*)d_in[0];
    const float* noise      = (const float*)d_in[1];
    const float* decays     = (const float*)d_in[2];
    const float* mixer      = (const float*)d_in[3];
    const float* transfers  = (const float*)d_in[4];
    const float* mixer_mats = (const float*)d_in[5];
    const float* gains      = (const float*)d_in[6];
    const float* fb         = (const float*)d_in[7];
    float* out = (float*)d_out;

    cudaFuncSetAttribute(sweep_kernel, cudaFuncAttributeMaxDynamicSharedMemorySize, SWEEP_BYTES);

    init_kernel<<<64, 256>>>(decays);
    ident_kernel<<<NL, 256>>>(mixer_mats);
    tmat_kernel<<<NL*NC, 256>>>(transfers, fb);
    x0_kernel<<<(BC*NT/4 + 255)/256, 256>>>(sig, noise);

    for (int l = 0; l < NL; l++) {
        dim3 mg(NT/256, NB);
        mix_kernel<<<mg, 256>>>(l, mixer_mats + l*NC*NC);   // early-exits when identity
        fwd_kernel<<<BC*FR, 256>>>(l);
        carry_kernel<<<(BC*KB + 255)/256, 256>>>(l);
        sweep_kernel<<<BC*CH, 256, SWEEP_BYTES>>>(l, gains);
        stitch_kernel<<<(BC*CH*512 + 255)/256, 256>>>(l, gains);
    }

    final_kernel<<<(NB*NT/4 + 255)/256, 256>>>(mixer, out);
    if (out_size >= NB*NT + NB*NC*NFR)
        copy_sig_kernel<<<(NB*NC*NFR + 255)/256, 256>>>(sig, out);
}